// round 14
// baseline (speedup 1.0000x reference)
#include <cuda_runtime.h>
#include <cstdint>

#define S_   2048
#define B_   2
#define C_   512
#define H_   8
#define CC_  64
#define M_   (S_*B_)      // 4096
#define K3C_ (3*C_)       // 1536

#define NSPL 4            // max key-splits per query tile
#define TPS  8            // max key tiles (of 64) per split
#define NQT  (S_/64)      // 32 query tiles

// Scratch (static device globals — no dynamic allocation allowed)
__device__ float g_qkv[(size_t)M_ * K3C_];   // post-GEMM1: q(prescaled,tf32), k,v(tf32)
__device__ float g_attn[(size_t)M_ * C_];    // xpe (tf32) scratch, then attn out (tf32)
__device__ float g_po[(size_t)NQT * NSPL * B_ * H_ * 64 * 64];  // partial O
__device__ float g_pm[(size_t)NQT * NSPL * B_ * H_ * 64];       // partial m (log2)
__device__ float g_pl[(size_t)NQT * NSPL * B_ * H_ * 64];       // partial l

// ============================================================================
// helpers (portable PTX — no sm_103a-only instructions)
// ============================================================================
__device__ __forceinline__ uint32_t smem_u32(const void* p) {
    uint32_t a;
    asm("{ .reg .u64 t; cvta.to.shared.u64 t, %1; cvt.u32.u64 %0, t; }"
        : "=r"(a) : "l"(p));
    return a;
}

__device__ __forceinline__ uint32_t f2tf(float f) {
    uint32_t u;
    asm("cvt.rna.tf32.f32 %0, %1;" : "=r"(u) : "f"(f));
    return u;
}
__device__ __forceinline__ float f2tf_f(float f) {
    return __uint_as_float(f2tf(f));
}

__device__ __forceinline__ float ex2(float x) {
    float y;
    asm("ex2.approx.f32 %0, %1;" : "=f"(y) : "f"(x));
    return y;
}

__device__ __forceinline__ void mma_tf32(float c[4], const uint32_t a[4],
                                         const uint32_t b[2]) {
    asm volatile(
        "mma.sync.aligned.m16n8k8.row.col.f32.tf32.tf32.f32 "
        "{%0,%1,%2,%3}, {%4,%5,%6,%7}, {%8,%9}, {%0,%1,%2,%3};"
        : "+f"(c[0]), "+f"(c[1]), "+f"(c[2]), "+f"(c[3])
        : "r"(a[0]), "r"(a[1]), "r"(a[2]), "r"(a[3]), "r"(b[0]), "r"(b[1]));
}

__device__ __forceinline__ void cp_async16(uint32_t saddr, const void* gptr) {
    asm volatile("cp.async.cg.shared.global [%0], [%1], 16;"
                 :: "r"(saddr), "l"(gptr));
}
__device__ __forceinline__ void cp_commit() {
    asm volatile("cp.async.commit_group;");
}
template<int N>
__device__ __forceinline__ void cp_wait() {
    asm volatile("cp.async.wait_group %0;" :: "n"(N));
}

#define QSCALE 0.18033688f   // (1/sqrt(64)) * log2(e)

// ============================================================================
// x + pe -> g_attn (tf32-rounded), vectorized
// ============================================================================
__global__ void __launch_bounds__(256)
add_pe(const float4* __restrict__ x, const float4* __restrict__ pe,
       float4* __restrict__ out)
{
    int i = blockIdx.x * 256 + threadIdx.x;
    float4 a = x[i], p = pe[i];
    out[i] = make_float4(f2tf_f(a.x + p.x), f2tf_f(a.y + p.y),
                         f2tf_f(a.z + p.z), f2tf_f(a.w + p.w));
}

// ============================================================================
// cp.async 2-stage pipelined HMMA tf32 GEMM (NT) — 256 thr, 128x128 tiles.
// SINGLE sync per K-chunk: wait -> sync -> issue(c+1) -> compute(c).
// (The sync proves all warps finished reading stage c-1, which is the buffer
// issue(c+1) overwrites.) A pre-rounded tf32; W raw fp32 (cvt on B frags).
// QKV_OUT: epilogue rounds to tf32 and prescales q columns by QSCALE.
// ============================================================================
#define GBM 128
#define GBN 128
#define GBK 32
#define GST 36
#define GEMM_SMEM (2 * (GBM * GST + GBN * GST) * 4)

template<bool QKV_OUT>
__global__ void __launch_bounds__(256, 2)
gemm_pipe(const float* __restrict__ A, const float* __restrict__ W,
          const float* __restrict__ bias, float* __restrict__ out,
          int Mdim, int Ndim, int Kdim)
{
    extern __shared__ uint32_t sm[];
    uint32_t* As = sm;
    uint32_t* Bs = sm + 2 * GBM * GST;

    const int tid  = threadIdx.x;
    const int warp = tid >> 5;
    const int lane = tid & 31;
    const int g    = lane >> 2;
    const int tig  = lane & 3;
    const int wm   = warp & 1;
    const int wn   = warp >> 1;
    const int m0 = blockIdx.y * GBM;
    const int n0 = blockIdx.x * GBN;

    const uint32_t sA = smem_u32(As);
    const uint32_t sB = smem_u32(Bs);

    const int r_ld = tid >> 3;
    const int q_ld = tid & 7;

    auto issue = [&](int stage, int k0) {
        const uint32_t offA = (uint32_t)(stage * GBM * GST) * 4;
        const uint32_t offB = (uint32_t)(stage * GBN * GST) * 4;
        #pragma unroll
        for (int t = 0; t < 4; t++) {
            int r = r_ld + t * 32;
            uint32_t so = (uint32_t)(r * GST + q_ld * 4) * 4;
            cp_async16(sA + offA + so, &A[(size_t)(m0 + r) * Kdim + k0 + q_ld * 4]);
            cp_async16(sB + offB + so, &W[(size_t)(n0 + r) * Kdim + k0 + q_ld * 4]);
        }
        cp_commit();
    };

    float acc[4][4][4] = {};
    const int NC = Kdim / GBK;

    issue(0, 0);

    for (int c = 0; c < NC; c++) {
        cp_wait<0>();
        __syncthreads();
        if (c + 1 < NC) issue((c + 1) & 1, (c + 1) * GBK);

        const uint32_t* Ac = As + (c & 1) * GBM * GST;
        const uint32_t* Bc = Bs + (c & 1) * GBN * GST;

        #pragma unroll
        for (int ks = 0; ks < 4; ks++) {
            const int kb = ks * 8;
            uint32_t a[4][4], b[4][2];
            #pragma unroll
            for (int i = 0; i < 4; i++) {
                const int row = wm * 64 + i * 16;
                a[i][0] = Ac[(row + g)     * GST + kb + tig];
                a[i][1] = Ac[(row + g + 8) * GST + kb + tig];
                a[i][2] = Ac[(row + g)     * GST + kb + tig + 4];
                a[i][3] = Ac[(row + g + 8) * GST + kb + tig + 4];
            }
            #pragma unroll
            for (int j = 0; j < 4; j++) {
                const int col = wn * 32 + j * 8;
                b[j][0] = f2tf(__uint_as_float(Bc[(col + g) * GST + kb + tig]));
                b[j][1] = f2tf(__uint_as_float(Bc[(col + g) * GST + kb + tig + 4]));
            }
            #pragma unroll
            for (int i = 0; i < 4; i++)
                #pragma unroll
                for (int j = 0; j < 4; j++)
                    mma_tf32(acc[i][j], a[i], b[j]);
        }
    }

    const float osc = (QKV_OUT && n0 < C_) ? QSCALE : 1.0f;
    #pragma unroll
    for (int i = 0; i < 4; i++) {
        const int row = m0 + wm * 64 + i * 16 + g;
        #pragma unroll
        for (int j = 0; j < 4; j++) {
            const int col = n0 + wn * 32 + j * 8 + 2 * tig;
            float2 bv = *(const float2*)&bias[col];
            float v0 = acc[i][j][0] + bv.x, v1 = acc[i][j][1] + bv.y;
            float v2 = acc[i][j][2] + bv.x, v3 = acc[i][j][3] + bv.y;
            if (QKV_OUT) {
                v0 = f2tf_f(v0 * osc); v1 = f2tf_f(v1 * osc);
                v2 = f2tf_f(v2 * osc); v3 = f2tf_f(v3 * osc);
            }
            *(float2*)&out[(size_t)row * Ndim + col]       = make_float2(v0, v1);
            *(float2*)&out[(size_t)(row + 8) * Ndim + col] = make_float2(v2, v3);
        }
    }
}

// ============================================================================
// Split-K flash attention partial kernel (HMMA tf32, cp.async 2-stage).
// Grid: (qt=32, bh=16, split=4). Splits are BALANCED: split s of nsp gets
// nt/nsp (+1 for s < nt%nsp) tiles. Writes partial (O, m, l) to scratch.
// ============================================================================
#define AST 68
#define VST 72
#define KTILE (64 * AST)
#define VTILE (64 * VST)
#define ATT_SMEM (2 * (KTILE + VTILE) * 4)

__global__ void __launch_bounds__(128)
attn_part()
{
    extern __shared__ uint32_t sm[];
    uint32_t* Ks = sm;                 // [2][KTILE]
    uint32_t* Vs = sm + 2 * KTILE;     // [2][VTILE]

    const int tid  = threadIdx.x;
    const int warp = tid >> 5;
    const int lane = tid & 31;
    const int g    = lane >> 2;
    const int tig  = lane & 3;
    const int qt = blockIdx.x;
    const int bh = blockIdx.y;
    const int b  = bh >> 3;
    const int h  = bh & 7;
    const int sp = blockIdx.z;

    const int nt  = qt + 1;                    // total key tiles for this qt
    const int nsp = (nt + TPS - 1) / TPS;      // active splits
    if (sp >= nsp) return;
    // balanced partition: split s gets base (+1 if s < rem) tiles
    const int base = nt / nsp;
    const int rem  = nt % nsp;
    const int tstart = sp * base + min(sp, rem);
    const int tend   = tstart + base + (sp < rem ? 1 : 0);
    const int q0 = qt * 64;
    const int rbase = warp * 16;

    const uint32_t sK = smem_u32(Ks);
    const uint32_t sV = smem_u32(Vs);

    auto issue = [&](int stage, int t0) {
        const uint32_t kb = sK + (uint32_t)(stage * KTILE) * 4;
        const uint32_t vb = sV + (uint32_t)(stage * VTILE) * 4;
        #pragma unroll
        for (int i = tid; i < 64 * 16; i += 128) {
            int r = i >> 4, c4 = i & 15;
            const float* gp = &g_qkv[((size_t)(t0 + r) * B_ + b) * K3C_ + h * CC_ + c4 * 4];
            cp_async16(kb + (uint32_t)(r * AST + c4 * 4) * 4, gp + C_);
            cp_async16(vb + (uint32_t)(r * VST + c4 * 4) * 4, gp + 2 * C_);
        }
        cp_commit();
    };

    issue(0, tstart * 64);

    // ---- Stage Q (prescaled tf32) via stage-1 K area, lift to registers ----
    uint32_t* Qst = Ks + KTILE;
    for (int i = tid; i < 64 * 16; i += 128) {
        int r = i >> 4, c4 = i & 15;
        *(uint4*)&Qst[r * AST + c4 * 4] =
            *(const uint4*)&g_qkv[((size_t)(q0 + r) * B_ + b) * K3C_ + h * CC_ + c4 * 4];
    }
    __syncthreads();

    uint32_t qf[8][4];
    #pragma unroll
    for (int kb = 0; kb < 8; kb++) {
        qf[kb][0] = Qst[(rbase + g)     * AST + kb * 8 + tig];
        qf[kb][1] = Qst[(rbase + g + 8) * AST + kb * 8 + tig];
        qf[kb][2] = Qst[(rbase + g)     * AST + kb * 8 + tig + 4];
        qf[kb][3] = Qst[(rbase + g + 8) * AST + kb * 8 + tig + 4];
    }

    float o[8][4] = {};
    float m0 = -1e30f, m1 = -1e30f;
    float l0 = 0.0f,   l1 = 0.0f;

    for (int ti = tstart; ti < tend; ti++) {
        const int cur = (ti - tstart) & 1;
        cp_wait<0>();
        __syncthreads();
        if (ti + 1 < tend) issue(cur ^ 1, (ti + 1) * 64);

        const uint32_t* Kc = Ks + cur * KTILE;
        const uint32_t* Vc = Vs + cur * VTILE;

        // ---- S = Q K^T (cvt-free) ----
        float s[8][4];
        #pragma unroll
        for (int j = 0; j < 8; j++) { s[j][0] = s[j][1] = s[j][2] = s[j][3] = 0.0f; }
        #pragma unroll
        for (int kb = 0; kb < 8; kb++) {
            #pragma unroll
            for (int j = 0; j < 8; j++) {
                uint32_t bf[2];
                bf[0] = Kc[(j * 8 + g) * AST + kb * 8 + tig];
                bf[1] = Kc[(j * 8 + g) * AST + kb * 8 + tig + 4];
                mma_tf32(s[j], qf[kb], bf);
            }
        }

        // ---- causal mask (diagonal tile only) ----
        if (ti == qt) {
            const int r0 = rbase + g;
            #pragma unroll
            for (int j = 0; j < 8; j++) {
                int t = j * 8 + 2 * tig;
                if (t     > r0)     s[j][0] = -1e30f;
                if (t + 1 > r0)     s[j][1] = -1e30f;
                if (t     > r0 + 8) s[j][2] = -1e30f;
                if (t + 1 > r0 + 8) s[j][3] = -1e30f;
            }
        }

        // ---- online softmax (exp2 domain) ----
        float a0 = -1e30f, a1 = -1e30f;
        #pragma unroll
        for (int j = 0; j < 8; j++) {
            a0 = fmaxf(a0, fmaxf(s[j][0], s[j][1]));
            a1 = fmaxf(a1, fmaxf(s[j][2], s[j][3]));
        }
        a0 = fmaxf(a0, __shfl_xor_sync(0xffffffffu, a0, 1));
        a0 = fmaxf(a0, __shfl_xor_sync(0xffffffffu, a0, 2));
        a1 = fmaxf(a1, __shfl_xor_sync(0xffffffffu, a1, 1));
        a1 = fmaxf(a1, __shfl_xor_sync(0xffffffffu, a1, 2));

        float mn0 = fmaxf(m0, a0);
        float mn1 = fmaxf(m1, a1);
        float sc0 = ex2(m0 - mn0);
        float sc1 = ex2(m1 - mn1);
        m0 = mn0; m1 = mn1;
        l0 *= sc0; l1 *= sc1;

        float p0[8], p1[8], p2[8], p3[8];
        #pragma unroll
        for (int j = 0; j < 8; j++) {
            p0[j] = f2tf_f(ex2(s[j][0] - mn0));
            p1[j] = f2tf_f(ex2(s[j][1] - mn0));
            p2[j] = f2tf_f(ex2(s[j][2] - mn1));
            p3[j] = f2tf_f(ex2(s[j][3] - mn1));
            l0 += p0[j] + p1[j];
            l1 += p2[j] + p3[j];
            o[j][0] *= sc0; o[j][1] *= sc0; o[j][2] *= sc1; o[j][3] *= sc1;
        }

        // ---- stage P into this warp's rows of current K buffer (K dead) ----
        __syncthreads();
        uint32_t* pw = (uint32_t*)Kc + rbase * AST;
        #pragma unroll
        for (int j = 0; j < 8; j++) {
            *(uint2*)&pw[(g)     * AST + j * 8 + 2 * tig] =
                make_uint2(__float_as_uint(p0[j]), __float_as_uint(p1[j]));
            *(uint2*)&pw[(g + 8) * AST + j * 8 + 2 * tig] =
                make_uint2(__float_as_uint(p2[j]), __float_as_uint(p3[j]));
        }
        __syncwarp();

        // ---- O += P V (cvt-free) ----
        #pragma unroll
        for (int kt = 0; kt < 8; kt++) {
            uint32_t af[4];
            af[0] = pw[(g)     * AST + kt * 8 + tig];
            af[1] = pw[(g + 8) * AST + kt * 8 + tig];
            af[2] = pw[(g)     * AST + kt * 8 + tig + 4];
            af[3] = pw[(g + 8) * AST + kt * 8 + tig + 4];
            #pragma unroll
            for (int j = 0; j < 8; j++) {
                uint32_t bf[2];
                bf[0] = Vc[(kt * 8 + tig)     * VST + j * 8 + g];
                bf[1] = Vc[(kt * 8 + tig + 4) * VST + j * 8 + g];
                mma_tf32(o[j], af, bf);
            }
        }
    }

    // ---- reduce l over the quad; write partials (no normalization) ----
    l0 += __shfl_xor_sync(0xffffffffu, l0, 1);
    l0 += __shfl_xor_sync(0xffffffffu, l0, 2);
    l1 += __shfl_xor_sync(0xffffffffu, l1, 1);
    l1 += __shfl_xor_sync(0xffffffffu, l1, 2);

    const size_t pb = (size_t)(qt * NSPL + sp) * 16 + bh;
    float* po = g_po + pb * (64 * 64);
    const int r_a = rbase + g;
    const int r_b = r_a + 8;
    #pragma unroll
    for (int j = 0; j < 8; j++) {
        const int col = j * 8 + 2 * tig;
        *(float2*)&po[r_a * 64 + col] = make_float2(o[j][0], o[j][1]);
        *(float2*)&po[r_b * 64 + col] = make_float2(o[j][2], o[j][3]);
    }
    if (tig == 0) {
        g_pm[pb * 64 + r_a] = m0;
        g_pl[pb * 64 + r_a] = l0;
        g_pm[pb * 64 + r_b] = m1;
        g_pl[pb * 64 + r_b] = l1;
    }
}

// ============================================================================
// Merge partials: out = (sum_s w_s O_s) / (sum_s w_s l_s), w_s = 2^(m_s - m*).
// Grid (qt=32, bh=16), 256 threads: thread = (row 0..63) x (colgroup 0..3).
// Output tf32-rounded so GEMM3 A-loads stay cvt-free.
// ============================================================================
__global__ void __launch_bounds__(256)
attn_merge()
{
    const int qt = blockIdx.x;
    const int bh = blockIdx.y;
    const int b  = bh >> 3;
    const int h  = bh & 7;
    const int nsp = (qt + 1 + TPS - 1) / TPS;
    const int tid = threadIdx.x;
    const int row = tid >> 2;
    const int cg  = tid & 3;

    float ms[NSPL], ws[NSPL];
    float mstar = -1e30f;
    #pragma unroll
    for (int s = 0; s < NSPL; s++) {
        if (s < nsp) {
            const size_t pb = (size_t)(qt * NSPL + s) * 16 + bh;
            ms[s] = g_pm[pb * 64 + row];
            mstar = fmaxf(mstar, ms[s]);
        }
    }
    float lsum = 0.0f;
    #pragma unroll
    for (int s = 0; s < NSPL; s++) {
        if (s < nsp) {
            const size_t pb = (size_t)(qt * NSPL + s) * 16 + bh;
            ws[s] = ex2(ms[s] - mstar);
            lsum += ws[s] * g_pl[pb * 64 + row];
        }
    }
    const float inv = 1.0f / lsum;

    const int q = qt * 64 + row;
    float* outp = g_attn + ((size_t)q * B_ + b) * C_ + h * CC_ + cg * 16;
    #pragma unroll
    for (int c4 = 0; c4 < 4; c4++) {
        float ax = 0, ay = 0, az = 0, aw = 0;
        #pragma unroll
        for (int s = 0; s < NSPL; s++) {
            if (s < nsp) {
                const size_t pb = (size_t)(qt * NSPL + s) * 16 + bh;
                float4 v = *(const float4*)&g_po[pb * (64 * 64) + row * 64 + cg * 16 + c4 * 4];
                ax += ws[s] * v.x; ay += ws[s] * v.y;
                az += ws[s] * v.z; aw += ws[s] * v.w;
            }
        }
        *(float4*)&outp[c4 * 4] = make_float4(f2tf_f(ax * inv), f2tf_f(ay * inv),
                                              f2tf_f(az * inv), f2tf_f(aw * inv));
    }
}

// ============================================================================
// Inputs (metadata order): x, pe, content_mask, pad, Wqkv, bqkv, Wc, bc
// content_mask is strict-causal (t > s) -> applied analytically; pad unused.
// ============================================================================
extern "C" void kernel_launch(void* const* d_in, const int* in_sizes, int n_in,
                              void* d_out, int out_size)
{
    const float* x    = (const float*)d_in[0];
    const float* pe   = (const float*)d_in[1];
    const float* Wqkv = (const float*)d_in[4];
    const float* bqkv = (const float*)d_in[5];
    const float* Wc   = (const float*)d_in[6];
    const float* bc   = (const float*)d_in[7];
    float* out = (float*)d_out;

    float *qkv, *attn;
    cudaGetSymbolAddress((void**)&qkv,  g_qkv);
    cudaGetSymbolAddress((void**)&attn, g_attn);

    cudaFuncSetAttribute(gemm_pipe<true>,
                         cudaFuncAttributeMaxDynamicSharedMemorySize, GEMM_SMEM);
    cudaFuncSetAttribute(gemm_pipe<false>,
                         cudaFuncAttributeMaxDynamicSharedMemorySize, GEMM_SMEM);
    cudaFuncSetAttribute(attn_part,
                         cudaFuncAttributeMaxDynamicSharedMemorySize, ATT_SMEM);

    // 0) xpe = tf32(x + pe)  (into g_attn scratch)
    add_pe<<<(M_ * C_ / 4) / 256, 256>>>(
        (const float4*)x, (const float4*)pe, (float4*)attn);

    // 1) qkv = xpe @ Wqkv^T + bqkv  -> q prescaled, all tf32
    gemm_pipe<true><<<dim3(K3C_ / GBN, M_ / GBM), 256, GEMM_SMEM>>>(
        attn, Wqkv, bqkv, qkv, M_, K3C_, C_);

    // 2a) split-K flash attention partials (balanced splits)
    attn_part<<<dim3(NQT, B_ * H_, NSPL), 128, ATT_SMEM>>>();

    // 2b) merge partials -> g_attn (tf32)
    attn_merge<<<dim3(NQT, B_ * H_), 256>>>();

    // 3) out = attn @ Wc^T + bc
    gemm_pipe<false><<<dim3(C_ / GBN, M_ / GBM), 256, GEMM_SMEM>>>(
        attn, Wc, bc, out, M_, C_, C_);
}

// round 15
// speedup vs baseline: 1.1504x; 1.1504x over previous
#include <cuda_runtime.h>
#include <cuda_fp16.h>
#include <cstdint>

#define S_   2048
#define B_   2
#define C_   512
#define H_   8
#define CC_  64
#define M_   (S_*B_)      // 4096
#define K3C_ (3*C_)       // 1536

#define NSPL 4            // max key-splits per query tile
#define TPS  8            // max key tiles (of 64) per split
#define NQT  (S_/64)      // 32 query tiles

// Scratch (static device globals — no dynamic allocation allowed)
__device__ float  g_qkv[(size_t)M_ * K3C_];   // fp32 tf32-rounded (q prescaled)
__device__ __half g_xh[(size_t)M_ * C_];      // xpe (fp16), then attn out (fp16)
__device__ __half g_wqkvh[(size_t)K3C_ * C_]; // Wqkv fp16
__device__ __half g_wch[(size_t)C_ * C_];     // Wc fp16
__device__ float  g_po[(size_t)NQT * NSPL * B_ * H_ * 64 * 64];
__device__ float  g_pm[(size_t)NQT * NSPL * B_ * H_ * 64];
__device__ float  g_pl[(size_t)NQT * NSPL * B_ * H_ * 64];

// ============================================================================
// helpers (portable PTX — no sm_103a-only instructions)
// ============================================================================
__device__ __forceinline__ uint32_t smem_u32(const void* p) {
    uint32_t a;
    asm("{ .reg .u64 t; cvta.to.shared.u64 t, %1; cvt.u32.u64 %0, t; }"
        : "=r"(a) : "l"(p));
    return a;
}

__device__ __forceinline__ uint32_t f2tf(float f) {
    uint32_t u;
    asm("cvt.rna.tf32.f32 %0, %1;" : "=r"(u) : "f"(f));
    return u;
}
__device__ __forceinline__ float f2tf_f(float f) {
    return __uint_as_float(f2tf(f));
}

__device__ __forceinline__ float ex2(float x) {
    float y;
    asm("ex2.approx.f32 %0, %1;" : "=f"(y) : "f"(x));
    return y;
}

__device__ __forceinline__ void mma_tf32(float c[4], const uint32_t a[4],
                                         const uint32_t b[2]) {
    asm volatile(
        "mma.sync.aligned.m16n8k8.row.col.f32.tf32.tf32.f32 "
        "{%0,%1,%2,%3}, {%4,%5,%6,%7}, {%8,%9}, {%0,%1,%2,%3};"
        : "+f"(c[0]), "+f"(c[1]), "+f"(c[2]), "+f"(c[3])
        : "r"(a[0]), "r"(a[1]), "r"(a[2]), "r"(a[3]), "r"(b[0]), "r"(b[1]));
}

__device__ __forceinline__ void mma_f16(float c[4], const uint32_t a[4],
                                        const uint32_t b[2]) {
    asm volatile(
        "mma.sync.aligned.m16n8k16.row.col.f32.f16.f16.f32 "
        "{%0,%1,%2,%3}, {%4,%5,%6,%7}, {%8,%9}, {%0,%1,%2,%3};"
        : "+f"(c[0]), "+f"(c[1]), "+f"(c[2]), "+f"(c[3])
        : "r"(a[0]), "r"(a[1]), "r"(a[2]), "r"(a[3]), "r"(b[0]), "r"(b[1]));
}

__device__ __forceinline__ void cp_async16(uint32_t saddr, const void* gptr) {
    asm volatile("cp.async.cg.shared.global [%0], [%1], 16;"
                 :: "r"(saddr), "l"(gptr));
}
__device__ __forceinline__ void cp_commit() {
    asm volatile("cp.async.commit_group;");
}
template<int N>
__device__ __forceinline__ void cp_wait() {
    asm volatile("cp.async.wait_group %0;" :: "n"(N));
}

#define QSCALE 0.18033688f   // (1/sqrt(64)) * log2(e)

// ============================================================================
// prep: xpe = fp16(x+pe); weights -> fp16
// ============================================================================
__global__ void __launch_bounds__(256)
add_pe(const float4* __restrict__ x, const float4* __restrict__ pe,
       uint2* __restrict__ out)
{
    int i = blockIdx.x * 256 + threadIdx.x;
    float4 a = x[i], p = pe[i];
    __half2 lo = __floats2half2_rn(a.x + p.x, a.y + p.y);
    __half2 hi = __floats2half2_rn(a.z + p.z, a.w + p.w);
    out[i] = make_uint2(*(uint32_t*)&lo, *(uint32_t*)&hi);
}

__global__ void __launch_bounds__(256)
conv_h(const float4* __restrict__ src, uint2* __restrict__ dst)
{
    int i = blockIdx.x * 256 + threadIdx.x;
    float4 v = src[i];
    __half2 lo = __floats2half2_rn(v.x, v.y);
    __half2 hi = __floats2half2_rn(v.z, v.w);
    dst[i] = make_uint2(*(uint32_t*)&lo, *(uint32_t*)&hi);
}

// ============================================================================
// fp16 HMMA GEMM (NT): out[m][n] = sum_k A[m][k]*W[n][k] + bias[n], fp32 accum.
// BM=BN=128, BK=32 halves; 256 thr = 8 warps 2(m) x 4(n); warp tile 64x32.
// m16n8k16 -> 2 k-steps/chunk, 32 MMAs/warp/chunk (half the tf32 count).
// Smem rows stride 40 halves (20 words): fragment words r*20+tig -> all
// 32 banks distinct. Static smem 2 stages x 2 x 128 x 80B = 40960 B.
// QKV_OUT: epilogue -> g_qkv fp32 tf32-rounded, q columns prescaled.
// ============================================================================
#define GBM 128
#define GBN 128
#define HROW 20   // words per smem row (40 halves)

template<bool QKV_OUT>
__global__ void __launch_bounds__(256, 2)
gemm_h(const __half* __restrict__ A, const __half* __restrict__ W,
       const float* __restrict__ bias, float* __restrict__ out,
       int Mdim, int Ndim, int Kdim)
{
    __shared__ uint32_t As[2][GBM * HROW];
    __shared__ uint32_t Bs[2][GBN * HROW];

    const int tid  = threadIdx.x;
    const int warp = tid >> 5;
    const int lane = tid & 31;
    const int g    = lane >> 2;
    const int tig  = lane & 3;
    const int wm   = warp & 1;
    const int wn   = warp >> 1;
    const int m0 = blockIdx.y * GBM;
    const int n0 = blockIdx.x * GBN;

    const uint32_t sA = smem_u32(As);
    const uint32_t sB = smem_u32(Bs);

    const int r_ld = tid >> 2;        // 0..63
    const int q_ld = tid & 3;         // 16B chunk within 64B row

    auto issue = [&](int stage, int k0) {
        const uint32_t offA = (uint32_t)stage * (GBM * HROW * 4);
        const uint32_t offB = (uint32_t)stage * (GBN * HROW * 4);
        #pragma unroll
        for (int t = 0; t < 2; t++) {
            int r = r_ld + t * 64;
            uint32_t so = (uint32_t)(r * 80 + q_ld * 16);
            cp_async16(sA + offA + so, A + (size_t)(m0 + r) * Kdim + k0 + q_ld * 8);
            cp_async16(sB + offB + so, W + (size_t)(n0 + r) * Kdim + k0 + q_ld * 8);
        }
        cp_commit();
    };

    float acc[4][4][4] = {};
    const int NC = Kdim / 32;

    issue(0, 0);

    for (int c = 0; c < NC; c++) {
        cp_wait<0>();
        __syncthreads();
        if (c + 1 < NC) issue((c + 1) & 1, (c + 1) * 32);

        const uint32_t* Ac = As[c & 1];
        const uint32_t* Bc = Bs[c & 1];

        #pragma unroll
        for (int ks = 0; ks < 2; ks++) {
            const int kw = ks * 8;    // word offset of this k-step (16 halves)
            uint32_t a[4][4], b[4][2];
            #pragma unroll
            for (int i = 0; i < 4; i++) {
                const int row = wm * 64 + i * 16;
                a[i][0] = Ac[(row + g)     * HROW + kw + tig];
                a[i][1] = Ac[(row + g + 8) * HROW + kw + tig];
                a[i][2] = Ac[(row + g)     * HROW + kw + 4 + tig];
                a[i][3] = Ac[(row + g + 8) * HROW + kw + 4 + tig];
            }
            #pragma unroll
            for (int j = 0; j < 4; j++) {
                const int col = wn * 32 + j * 8;
                b[j][0] = Bc[(col + g) * HROW + kw + tig];
                b[j][1] = Bc[(col + g) * HROW + kw + 4 + tig];
            }
            #pragma unroll
            for (int i = 0; i < 4; i++)
                #pragma unroll
                for (int j = 0; j < 4; j++)
                    mma_f16(acc[i][j], a[i], b[j]);
        }
    }

    const float osc = (QKV_OUT && n0 < C_) ? QSCALE : 1.0f;
    #pragma unroll
    for (int i = 0; i < 4; i++) {
        const int row = m0 + wm * 64 + i * 16 + g;
        #pragma unroll
        for (int j = 0; j < 4; j++) {
            const int col = n0 + wn * 32 + j * 8 + 2 * tig;
            float2 bv = *(const float2*)&bias[col];
            float v0 = acc[i][j][0] + bv.x, v1 = acc[i][j][1] + bv.y;
            float v2 = acc[i][j][2] + bv.x, v3 = acc[i][j][3] + bv.y;
            if (QKV_OUT) {
                v0 = f2tf_f(v0 * osc); v1 = f2tf_f(v1 * osc);
                v2 = f2tf_f(v2 * osc); v3 = f2tf_f(v3 * osc);
            }
            *(float2*)&out[(size_t)row * Ndim + col]       = make_float2(v0, v1);
            *(float2*)&out[(size_t)(row + 8) * Ndim + col] = make_float2(v2, v3);
        }
    }
}

// ============================================================================
// Split-K flash attention partial kernel (tf32 HMMA, cp.async 2-stage) —
// unchanged from R13/R14 (validated). Reads g_qkv fp32 (tf32-rounded).
// ============================================================================
#define AST 68
#define VST 72
#define KTILE (64 * AST)
#define VTILE (64 * VST)
#define ATT_SMEM (2 * (KTILE + VTILE) * 4)

__global__ void __launch_bounds__(128)
attn_part()
{
    extern __shared__ uint32_t sm[];
    uint32_t* Ks = sm;                 // [2][KTILE]
    uint32_t* Vs = sm + 2 * KTILE;     // [2][VTILE]

    const int tid  = threadIdx.x;
    const int warp = tid >> 5;
    const int lane = tid & 31;
    const int g    = lane >> 2;
    const int tig  = lane & 3;
    const int qt = blockIdx.x;
    const int bh = blockIdx.y;
    const int b  = bh >> 3;
    const int h  = bh & 7;
    const int sp = blockIdx.z;

    const int nt  = qt + 1;
    const int nsp = (nt + TPS - 1) / TPS;
    if (sp >= nsp) return;
    const int base = nt / nsp;
    const int rem  = nt % nsp;
    const int tstart = sp * base + min(sp, rem);
    const int tend   = tstart + base + (sp < rem ? 1 : 0);
    const int q0 = qt * 64;
    const int rbase = warp * 16;

    const uint32_t sK = smem_u32(Ks);
    const uint32_t sV = smem_u32(Vs);

    auto issue = [&](int stage, int t0) {
        const uint32_t kb = sK + (uint32_t)(stage * KTILE) * 4;
        const uint32_t vb = sV + (uint32_t)(stage * VTILE) * 4;
        #pragma unroll
        for (int i = tid; i < 64 * 16; i += 128) {
            int r = i >> 4, c4 = i & 15;
            const float* gp = &g_qkv[((size_t)(t0 + r) * B_ + b) * K3C_ + h * CC_ + c4 * 4];
            cp_async16(kb + (uint32_t)(r * AST + c4 * 4) * 4, gp + C_);
            cp_async16(vb + (uint32_t)(r * VST + c4 * 4) * 4, gp + 2 * C_);
        }
        cp_commit();
    };

    issue(0, tstart * 64);

    uint32_t* Qst = Ks + KTILE;
    for (int i = tid; i < 64 * 16; i += 128) {
        int r = i >> 4, c4 = i & 15;
        *(uint4*)&Qst[r * AST + c4 * 4] =
            *(const uint4*)&g_qkv[((size_t)(q0 + r) * B_ + b) * K3C_ + h * CC_ + c4 * 4];
    }
    __syncthreads();

    uint32_t qf[8][4];
    #pragma unroll
    for (int kb = 0; kb < 8; kb++) {
        qf[kb][0] = Qst[(rbase + g)     * AST + kb * 8 + tig];
        qf[kb][1] = Qst[(rbase + g + 8) * AST + kb * 8 + tig];
        qf[kb][2] = Qst[(rbase + g)     * AST + kb * 8 + tig + 4];
        qf[kb][3] = Qst[(rbase + g + 8) * AST + kb * 8 + tig + 4];
    }

    float o[8][4] = {};
    float m0 = -1e30f, m1 = -1e30f;
    float l0 = 0.0f,   l1 = 0.0f;

    for (int ti = tstart; ti < tend; ti++) {
        const int cur = (ti - tstart) & 1;
        cp_wait<0>();
        __syncthreads();
        if (ti + 1 < tend) issue(cur ^ 1, (ti + 1) * 64);

        const uint32_t* Kc = Ks + cur * KTILE;
        const uint32_t* Vc = Vs + cur * VTILE;

        float s[8][4];
        #pragma unroll
        for (int j = 0; j < 8; j++) { s[j][0] = s[j][1] = s[j][2] = s[j][3] = 0.0f; }
        #pragma unroll
        for (int kb = 0; kb < 8; kb++) {
            #pragma unroll
            for (int j = 0; j < 8; j++) {
                uint32_t bf[2];
                bf[0] = Kc[(j * 8 + g) * AST + kb * 8 + tig];
                bf[1] = Kc[(j * 8 + g) * AST + kb * 8 + tig + 4];
                mma_tf32(s[j], qf[kb], bf);
            }
        }

        if (ti == qt) {
            const int r0 = rbase + g;
            #pragma unroll
            for (int j = 0; j < 8; j++) {
                int t = j * 8 + 2 * tig;
                if (t     > r0)     s[j][0] = -1e30f;
                if (t + 1 > r0)     s[j][1] = -1e30f;
                if (t     > r0 + 8) s[j][2] = -1e30f;
                if (t + 1 > r0 + 8) s[j][3] = -1e30f;
            }
        }

        float a0 = -1e30f, a1 = -1e30f;
        #pragma unroll
        for (int j = 0; j < 8; j++) {
            a0 = fmaxf(a0, fmaxf(s[j][0], s[j][1]));
            a1 = fmaxf(a1, fmaxf(s[j][2], s[j][3]));
        }
        a0 = fmaxf(a0, __shfl_xor_sync(0xffffffffu, a0, 1));
        a0 = fmaxf(a0, __shfl_xor_sync(0xffffffffu, a0, 2));
        a1 = fmaxf(a1, __shfl_xor_sync(0xffffffffu, a1, 1));
        a1 = fmaxf(a1, __shfl_xor_sync(0xffffffffu, a1, 2));

        float mn0 = fmaxf(m0, a0);
        float mn1 = fmaxf(m1, a1);
        float sc0 = ex2(m0 - mn0);
        float sc1 = ex2(m1 - mn1);
        m0 = mn0; m1 = mn1;
        l0 *= sc0; l1 *= sc1;

        float p0[8], p1[8], p2[8], p3[8];
        #pragma unroll
        for (int j = 0; j < 8; j++) {
            p0[j] = f2tf_f(ex2(s[j][0] - mn0));
            p1[j] = f2tf_f(ex2(s[j][1] - mn0));
            p2[j] = f2tf_f(ex2(s[j][2] - mn1));
            p3[j] = f2tf_f(ex2(s[j][3] - mn1));
            l0 += p0[j] + p1[j];
            l1 += p2[j] + p3[j];
            o[j][0] *= sc0; o[j][1] *= sc0; o[j][2] *= sc1; o[j][3] *= sc1;
        }

        __syncthreads();
        uint32_t* pw = (uint32_t*)Kc + rbase * AST;
        #pragma unroll
        for (int j = 0; j < 8; j++) {
            *(uint2*)&pw[(g)     * AST + j * 8 + 2 * tig] =
                make_uint2(__float_as_uint(p0[j]), __float_as_uint(p1[j]));
            *(uint2*)&pw[(g + 8) * AST + j * 8 + 2 * tig] =
                make_uint2(__float_as_uint(p2[j]), __float_as_uint(p3[j]));
        }
        __syncwarp();

        #pragma unroll
        for (int kt = 0; kt < 8; kt++) {
            uint32_t af[4];
            af[0] = pw[(g)     * AST + kt * 8 + tig];
            af[1] = pw[(g + 8) * AST + kt * 8 + tig];
            af[2] = pw[(g)     * AST + kt * 8 + tig + 4];
            af[3] = pw[(g + 8) * AST + kt * 8 + tig + 4];
            #pragma unroll
            for (int j = 0; j < 8; j++) {
                uint32_t bf[2];
                bf[0] = Vc[(kt * 8 + tig)     * VST + j * 8 + g];
                bf[1] = Vc[(kt * 8 + tig + 4) * VST + j * 8 + g];
                mma_tf32(o[j], af, bf);
            }
        }
    }

    l0 += __shfl_xor_sync(0xffffffffu, l0, 1);
    l0 += __shfl_xor_sync(0xffffffffu, l0, 2);
    l1 += __shfl_xor_sync(0xffffffffu, l1, 1);
    l1 += __shfl_xor_sync(0xffffffffu, l1, 2);

    const size_t pb = (size_t)(qt * NSPL + sp) * 16 + bh;
    float* po = g_po + pb * (64 * 64);
    const int r_a = rbase + g;
    const int r_b = r_a + 8;
    #pragma unroll
    for (int j = 0; j < 8; j++) {
        const int col = j * 8 + 2 * tig;
        *(float2*)&po[r_a * 64 + col] = make_float2(o[j][0], o[j][1]);
        *(float2*)&po[r_b * 64 + col] = make_float2(o[j][2], o[j][3]);
    }
    if (tig == 0) {
        g_pm[pb * 64 + r_a] = m0;
        g_pl[pb * 64 + r_a] = l0;
        g_pm[pb * 64 + r_b] = m1;
        g_pl[pb * 64 + r_b] = l1;
    }
}

// ============================================================================
// Merge partials -> g_xh as fp16 (GEMM3's A side).
// ============================================================================
__global__ void __launch_bounds__(256)
attn_merge()
{
    const int qt = blockIdx.x;
    const int bh = blockIdx.y;
    const int b  = bh >> 3;
    const int h  = bh & 7;
    const int nsp = (qt + 1 + TPS - 1) / TPS;
    const int tid = threadIdx.x;
    const int row = tid >> 2;
    const int cg  = tid & 3;

    float ms[NSPL], ws[NSPL];
    float mstar = -1e30f;
    #pragma unroll
    for (int s = 0; s < NSPL; s++) {
        if (s < nsp) {
            const size_t pb = (size_t)(qt * NSPL + s) * 16 + bh;
            ms[s] = g_pm[pb * 64 + row];
            mstar = fmaxf(mstar, ms[s]);
        }
    }
    float lsum = 0.0f;
    #pragma unroll
    for (int s = 0; s < NSPL; s++) {
        if (s < nsp) {
            const size_t pb = (size_t)(qt * NSPL + s) * 16 + bh;
            ws[s] = ex2(ms[s] - mstar);
            lsum += ws[s] * g_pl[pb * 64 + row];
        }
    }
    const float inv = 1.0f / lsum;

    const int q = qt * 64 + row;
    __half* outp = g_xh + ((size_t)q * B_ + b) * C_ + h * CC_ + cg * 16;
    #pragma unroll
    for (int c4 = 0; c4 < 4; c4++) {
        float ax = 0, ay = 0, az = 0, aw = 0;
        #pragma unroll
        for (int s = 0; s < NSPL; s++) {
            if (s < nsp) {
                const size_t pb = (size_t)(qt * NSPL + s) * 16 + bh;
                float4 v = *(const float4*)&g_po[pb * (64 * 64) + row * 64 + cg * 16 + c4 * 4];
                ax += ws[s] * v.x; ay += ws[s] * v.y;
                az += ws[s] * v.z; aw += ws[s] * v.w;
            }
        }
        __half2 lo = __floats2half2_rn(ax * inv, ay * inv);
        __half2 hi = __floats2half2_rn(az * inv, aw * inv);
        *(uint2*)&outp[c4 * 4] = make_uint2(*(uint32_t*)&lo, *(uint32_t*)&hi);
    }
}

// ============================================================================
// Inputs (metadata order): x, pe, content_mask, pad, Wqkv, bqkv, Wc, bc
// content_mask is strict-causal (t > s) -> applied analytically; pad unused.
// ============================================================================
extern "C" void kernel_launch(void* const* d_in, const int* in_sizes, int n_in,
                              void* d_out, int out_size)
{
    const float* x    = (const float*)d_in[0];
    const float* pe   = (const float*)d_in[1];
    const float* Wqkv = (const float*)d_in[4];
    const float* bqkv = (const float*)d_in[5];
    const float* Wc   = (const float*)d_in[6];
    const float* bc   = (const float*)d_in[7];
    float* out = (float*)d_out;

    float *qkv;
    __half *xh, *wqkvh, *wch;
    cudaGetSymbolAddress((void**)&qkv,   g_qkv);
    cudaGetSymbolAddress((void**)&xh,    g_xh);
    cudaGetSymbolAddress((void**)&wqkvh, g_wqkvh);
    cudaGetSymbolAddress((void**)&wch,   g_wch);

    cudaFuncSetAttribute(attn_part,
                         cudaFuncAttributeMaxDynamicSharedMemorySize, ATT_SMEM);

    // 0) prep: xpe = fp16(x+pe); weights -> fp16
    add_pe<<<(M_ * C_ / 4) / 256, 256>>>(
        (const float4*)x, (const float4*)pe, (uint2*)xh);
    conv_h<<<(K3C_ * C_ / 4) / 256, 256>>>((const float4*)Wqkv, (uint2*)wqkvh);
    conv_h<<<(C_ * C_ / 4) / 256, 256>>>((const float4*)Wc, (uint2*)wch);

    // 1) qkv = xpe @ Wqkv^T + bqkv  (fp16 MMA, fp32 accum) -> fp32 tf32-rounded
    gemm_h<true><<<dim3(K3C_ / GBN, M_ / GBM), 256>>>(
        xh, wqkvh, bqkv, qkv, M_, K3C_, C_);

    // 2a) split-K flash attention partials (tf32, unchanged)
    attn_part<<<dim3(NQT, B_ * H_, NSPL), 128, ATT_SMEM>>>();

    // 2b) merge partials -> g_xh (fp16)
    attn_merge<<<dim3(NQT, B_ * H_), 256>>>();

    // 3) out = attn @ Wc^T + bc  (fp16 MMA, fp32 accum) -> fp32
    gemm_h<false><<<dim3(C_ / GBN, M_ / GBM), 256>>>(
        xh, wch, bc, out, M_, C_, C_);
}